// round 12
// baseline (speedup 1.0000x reference)
#include <cuda_runtime.h>
#include <cstdint>

// Problem shape (fixed by the reference)
#define T_STEPS 5
#define BB 32
#define CC 128
#define HW 1024                    // 32*32
#define NPT (BB * CC * HW)         // 4,194,304 elements per timestep
#define N4  (NPT / 4)              // 1,048,576 float4 per timestep
#define NTHR 1024                  // threads per CTA (one CTA per channel)
#define NWARP (NTHR / 32)
#define BATCH_F4 (CC * HW / 4)     // 32768 float4 per batch slice
#define JSTRIDE  (4 * BATCH_F4)    // 131072: float4 stride between j-iterations
#define KTOT (T_STEPS * 8)         // 40 flat iterations

#define NSTAGE 3
#define STAGE_BYTES 32768          // one j-iteration of inputs (16KB xe + 16KB xi)
#define CARRY_BYTES (BB * HW * 4)  // 131072 B membrane carry
#define SMEM_DYN (CARRY_BYTES + NSTAGE * STAGE_BYTES)   // 229376 B

static constexpr float V_TH    = 0.5f;
static constexpr float W_DEC   = 0.5f;
static constexpr float LOWER_C = 0.2f - 0.03f;   // 0.17
static constexpr float UPPER_C = 0.2f + 0.03f;   // 0.23
static constexpr float EMA0    = 0.17f;
static constexpr float INV_N   = 1.0f / 32768.0f; // 1/(B*H*W)

__device__ __forceinline__ float sigmoidf(float x) {
    return 1.0f / (1.0f + expf(-x));
}

__device__ __forceinline__ uint32_t s2u(const void* p) {
    uint32_t a;
    asm("{ .reg .u64 t; cvta.to.shared.u64 t, %1; cvt.u32.u64 %0, t; }"
        : "=r"(a) : "l"(p));
    return a;
}
__device__ __forceinline__ void mbar_init(uint32_t a, uint32_t cnt) {
    asm volatile("mbarrier.init.shared.b64 [%0], %1;" :: "r"(a), "r"(cnt) : "memory");
}
__device__ __forceinline__ void mbar_expect_tx(uint32_t a, uint32_t bytes) {
    asm volatile("mbarrier.arrive.expect_tx.shared.b64 _, [%0], %1;"
                 :: "r"(a), "r"(bytes) : "memory");
}
__device__ __forceinline__ void mbar_arrive(uint32_t a) {
    asm volatile("mbarrier.arrive.shared.b64 _, [%0];" :: "r"(a) : "memory");
}
__device__ __forceinline__ void mbar_wait(uint32_t a, uint32_t parity) {
    asm volatile(
        "{\n\t"
        ".reg .pred P;\n\t"
        "WL_%=:\n\t"
        "mbarrier.try_wait.parity.acquire.cta.shared::cta.b64 P, [%0], %1, 0x989680;\n\t"
        "@P bra.uni WD_%=;\n\t"
        "bra.uni WL_%=;\n\t"
        "WD_%=:\n\t"
        "}"
        :: "r"(a), "r"(parity) : "memory");
}
__device__ __forceinline__ void bulk_g2s(uint32_t dst, const void* src,
                                         uint32_t bytes, uint32_t mbar) {
    asm volatile(
        "cp.async.bulk.shared::cta.global.mbarrier::complete_tx::bytes "
        "[%0], [%1], %2, [%3];"
        :: "r"(dst), "l"(src), "r"(bytes), "r"(mbar) : "memory");
}

// Prefetch stage for flat-iteration k2 (thread 0 only): 8 contiguous 4KB runs
// (4 batches x {xe, xi}) of channel c into stage k2%NSTAGE.
__device__ __forceinline__ void issue_stage(
    int k2, int c, const float* __restrict__ xe, const float* __restrict__ xi,
    uint32_t stage_a, const uint32_t* full_a, const uint32_t* empty_a)
{
    const int s = k2 % NSTAGE;
    if (k2 >= NSTAGE) mbar_wait(empty_a[s], ((k2 / NSTAGE) - 1) & 1);
    mbar_expect_tx(full_a[s], STAGE_BYTES);
    const int t2 = k2 >> 3, j2 = k2 & 7;
    const size_t base = (size_t)t2 * NPT + (size_t)(4 * j2) * (CC * HW)
                      + (size_t)c * HW;                  // float offset
    const uint32_t dst = stage_a + s * STAGE_BYTES;
    #pragma unroll
    for (int r = 0; r < 4; ++r) {
        bulk_g2s(dst +         r * 4096, xe + base + (size_t)r * (CC * HW), 4096, full_a[s]);
        bulk_g2s(dst + 16384 + r * 4096, xi + base + (size_t)r * (CC * HW), 4096, full_a[s]);
    }
}

// One CTA per channel; whole recurrence is channel-local (no cross-CTA comm).
// Inputs stream via cp.async.bulk into a 3-stage smem pipeline (prefetch 2
// iterations ahead, crossing step boundaries); membrane carry in smem.
__global__ __launch_bounds__(NTHR, 1)
void lif_all(const float* __restrict__ xe,
             const float* __restrict__ xi,
             const float* __restrict__ alpha_raw,
             const float* __restrict__ beta_raw,
             float* __restrict__ out)
{
    extern __shared__ char smem_raw[];
    float4* s_mem = reinterpret_cast<float4*>(smem_raw);        // carry
    char*   s_stage = smem_raw + CARRY_BYTES;                   // 3 stages
    __shared__ float s_wsum[NWARP];
    __shared__ float s_bw;
    __shared__ __align__(8) uint64_t s_full[NSTAGE], s_empty[NSTAGE];

    const int c    = blockIdx.x;               // channel
    const int tid  = threadIdx.x;
    const int lane = tid & 31;
    const int wid  = tid >> 5;

    uint32_t full_a[NSTAGE], empty_a[NSTAGE];
    #pragma unroll
    for (int s = 0; s < NSTAGE; ++s) {
        full_a[s]  = s2u(&s_full[s]);
        empty_a[s] = s2u(&s_empty[s]);
    }
    const uint32_t stage_a = s2u(s_stage);

    if (tid == 0) {
        #pragma unroll
        for (int s = 0; s < NSTAGE; ++s) {
            mbar_init(full_a[s], 1);           // tx-based completion
            mbar_init(empty_a[s], NWARP);      // one arrive per warp
        }
    }
    __syncthreads();                           // barriers visible before any copy

    if (tid == 0) { issue_stage(0, c, xe, xi, stage_a, full_a, empty_a);
                    issue_stage(1, c, xe, xi, stage_a, full_a, empty_a); }

    const float alpha = 4.0f * sigmoidf(__ldg(alpha_raw));
    const float beta  = sigmoidf(__ldg(beta_raw));

    // Thread's float4 index within a j-chunk: batch (tid>>8), offset tid&255
    const int g0 = (tid >> 8) * BATCH_F4 + c * (HW / 4) + (tid & 255);
    float4* out4 = reinterpret_cast<float4*>(out) + g0;

    // This thread's fixed offset inside a stage buffer
    const char* my_xe = s_stage + ((tid >> 8) << 12) + ((tid & 255) << 4);
    const char* my_xi = my_xe + 16384;

    float ema = EMA0;                          // maintained by (wid0,lane0) only
    float bw  = beta;                          // inhw starts at 0
    float cnt = 0.0f;

    #pragma unroll
    for (int k = 0; k < KTOT; ++k) {
        const int t = k >> 3;                  // step (compile-time)
        const int j = k & 7;                   // plane-group within step
        const int s = k % NSTAGE;

        if (tid == 0 && k + 2 < KTOT)
            issue_stage(k + 2, c, xe, xi, stage_a, full_a, empty_a);

        // Wait stage full (lane 0 polls; warp broadcast via syncwarp)
        if (lane == 0) mbar_wait(full_a[s], (k / NSTAGE) & 1);
        __syncwarp();

        const float4 e = *reinterpret_cast<const float4*>(my_xe + s * STAGE_BYTES);
        const float4 v = *reinterpret_cast<const float4*>(my_xi + s * STAGE_BYTES);

        // Release the stage (per-warp arrive, after this warp's reads)
        __syncwarp();
        if (lane == 0) mbar_arrive(empty_a[s]);

        float4 m = (t == 0) ? make_float4(0.f, 0.f, 0.f, 0.f)
                            : s_mem[j * NTHR + tid];
        float4 sp;

        m.x = W_DEC * m.x + e.x / (1.0f + alpha * v.x) - bw * v.x;
        sp.x = (m.x >= V_TH) ? 1.0f : 0.0f;  m.x -= V_TH * sp.x;
        m.y = W_DEC * m.y + e.y / (1.0f + alpha * v.y) - bw * v.y;
        sp.y = (m.y >= V_TH) ? 1.0f : 0.0f;  m.y -= V_TH * sp.y;
        m.z = W_DEC * m.z + e.z / (1.0f + alpha * v.z) - bw * v.z;
        sp.z = (m.z >= V_TH) ? 1.0f : 0.0f;  m.z -= V_TH * sp.z;
        m.w = W_DEC * m.w + e.w / (1.0f + alpha * v.w) - bw * v.w;
        sp.w = (m.w >= V_TH) ? 1.0f : 0.0f;  m.w -= V_TH * sp.w;

        __stcs(out4 + (size_t)t * N4 + (size_t)j * JSTRIDE, sp);

        if (t < T_STEPS - 1) {
            s_mem[j * NTHR + tid] = m;
            cnt += sp.x + sp.y + sp.z + sp.w;
        }

        // Step boundary: reduce channel spike count, update bw. Next step's
        // input stages are already in flight (issued at k-1, k).
        if (j == 7 && t < T_STEPS - 1) {
            float r = cnt;                     // integer-valued: exact any order
            #pragma unroll
            for (int off = 16; off > 0; off >>= 1)
                r += __shfl_down_sync(0xFFFFFFFFu, r, off);
            if (lane == 0) s_wsum[wid] = r;
            __syncthreads();
            if (wid == 0) {
                float x = s_wsum[lane];        // exactly 32 warps
                #pragma unroll
                for (int off = 16; off > 0; off >>= 1)
                    x += __shfl_down_sync(0xFFFFFFFFu, x, off);
                if (lane == 0) {
                    ema = 0.9f * ema + 0.1f * (x * INV_N);
                    const float inhw =
                        4.0f * (sigmoidf(LOWER_C - ema) - sigmoidf(ema - UPPER_C));
                    s_bw = beta * (1.0f - inhw);
                }
            }
            __syncthreads();
            bw  = s_bw;
            cnt = 0.0f;
        }
    }
}

extern "C" void kernel_launch(void* const* d_in, const int* in_sizes, int n_in,
                              void* d_out, int out_size)
{
    const float* xe = (const float*)d_in[0];  // x_exc  [T,B,C,H,W]
    const float* xi = (const float*)d_in[1];  // x_inh  [T,B,C,H,W]
    const float* ar = (const float*)d_in[2];  // alpha_raw scalar
    const float* br = (const float*)d_in[3];  // beta_raw scalar
    float* out = (float*)d_out;               // spikes [T,B,C,H,W]

    static bool attr_set = false;
    if (!attr_set) {
        cudaFuncSetAttribute(lif_all, cudaFuncAttributeMaxDynamicSharedMemorySize,
                             SMEM_DYN);
        attr_set = true;
    }
    lif_all<<<CC, NTHR, SMEM_DYN>>>(xe, xi, ar, br, out);
}